// round 1
// baseline (speedup 1.0000x reference)
#include <cuda_runtime.h>

#define B_   2
#define SQ_  2048
#define SK_  512
#define HID_ 1024
#define NH_  16
#define HD_  64

// Scratch (static __device__ globals: allowed, no runtime allocation)
__device__ float g_Qt[B_*NH_*HD_*SQ_];   // [bh][d][q], pre-scaled by 1/8
__device__ float g_Kt[B_*NH_*HD_*SK_];   // [bh][d][k]
__device__ float g_V [B_*NH_*SK_*HD_];   // [bh][k][d]

// ---------------------------------------------------------------------------
// GEMM: out = A(M x 1024) @ W^T, W is (1024 x 1024) row-major.
// y[m,n] = sum_k A[m,k] * W[n,k]   (NT gemm, K contiguous for both)
// MODE 0: out[((b*NH+h)*S + s)*HD + d]          (V layout)
// MODE 1: out[((b*NH+h)*HD + d)*S + s] * scale  (Q/K transposed layout)
// Tile 128x128x16, 256 threads, 8x8 micro-tile (split 4+4 with 64 offset).
// ---------------------------------------------------------------------------
template<int MODE>
__global__ void __launch_bounds__(256)
gemm_qkv(const float* __restrict__ A, const float* __restrict__ W,
         float* __restrict__ outp, int S, float scale)
{
    __shared__ float As[16][128];
    __shared__ float Bs[16][128];

    const int tid = threadIdx.x;
    const int tx  = tid & 15;
    const int ty  = tid >> 4;
    const int m0  = blockIdx.y * 128;
    const int n0  = blockIdx.x * 128;

    float acc[8][8];
    #pragma unroll
    for (int i = 0; i < 8; i++)
        #pragma unroll
        for (int j = 0; j < 8; j++) acc[i][j] = 0.0f;

    for (int kt = 0; kt < HID_ / 16; kt++) {
        const float* Ap = A + (size_t)m0 * HID_ + kt * 16;
        const float* Wp = W + (size_t)n0 * HID_ + kt * 16;
        // load A tile (128x16) and W tile (128x16), stored transposed [k][m]
        #pragma unroll
        for (int p = 0; p < 2; p++) {
            int idx = tid + p * 256;          // 0..511
            int row = idx >> 2;               // 0..127
            int c4  = (idx & 3) << 2;         // 0,4,8,12
            float4 va = *(const float4*)(Ap + (size_t)row * HID_ + c4);
            As[c4 + 0][row] = va.x; As[c4 + 1][row] = va.y;
            As[c4 + 2][row] = va.z; As[c4 + 3][row] = va.w;
            float4 vb = *(const float4*)(Wp + (size_t)row * HID_ + c4);
            Bs[c4 + 0][row] = vb.x; Bs[c4 + 1][row] = vb.y;
            Bs[c4 + 2][row] = vb.z; Bs[c4 + 3][row] = vb.w;
        }
        __syncthreads();

        #pragma unroll
        for (int k = 0; k < 16; k++) {
            float4 a0 = *(float4*)&As[k][ty * 4];
            float4 a1 = *(float4*)&As[k][64 + ty * 4];
            float4 b0 = *(float4*)&Bs[k][tx * 4];
            float4 b1 = *(float4*)&Bs[k][64 + tx * 4];
            float av[8] = {a0.x, a0.y, a0.z, a0.w, a1.x, a1.y, a1.z, a1.w};
            float bv[8] = {b0.x, b0.y, b0.z, b0.w, b1.x, b1.y, b1.z, b1.w};
            #pragma unroll
            for (int i = 0; i < 8; i++)
                #pragma unroll
                for (int j = 0; j < 8; j++)
                    acc[i][j] = fmaf(av[i], bv[j], acc[i][j]);
        }
        __syncthreads();
    }

    if (MODE == 0) {
        // V layout: [(b*NH+h)*S + s]*HD + d ; n-quads stay inside a head (HD=64)
        #pragma unroll
        for (int i = 0; i < 8; i++) {
            int m  = m0 + ((i < 4) ? (ty * 4 + i) : (64 + ty * 4 + (i - 4)));
            int bb = m / S;
            int s  = m - bb * S;
            #pragma unroll
            for (int jg = 0; jg < 2; jg++) {
                int n = n0 + jg * 64 + tx * 4;
                int h = n >> 6, d = n & 63;
                float4 v = make_float4(acc[i][jg*4+0] * scale, acc[i][jg*4+1] * scale,
                                       acc[i][jg*4+2] * scale, acc[i][jg*4+3] * scale);
                *(float4*)&outp[(((size_t)bb * NH_ + h) * S + s) * HD_ + d] = v;
            }
        }
    } else {
        // Transposed layout: [(b*NH+h)*HD + d]*S + s ; 4 consecutive m -> float4
        #pragma unroll
        for (int jg = 0; jg < 2; jg++) {
            #pragma unroll
            for (int j = 0; j < 4; j++) {
                int n = n0 + jg * 64 + tx * 4 + j;
                int h = n >> 6, d = n & 63;
                #pragma unroll
                for (int ig = 0; ig < 2; ig++) {
                    int m  = m0 + ig * 64 + ty * 4;
                    int bb = m / S;
                    int s  = m - bb * S;
                    float4 v = make_float4(acc[ig*4+0][jg*4+j] * scale,
                                           acc[ig*4+1][jg*4+j] * scale,
                                           acc[ig*4+2][jg*4+j] * scale,
                                           acc[ig*4+3][jg*4+j] * scale);
                    *(float4*)&outp[(((size_t)bb * NH_ + h) * HD_ + d) * S + s] = v;
                }
            }
        }
    }
}

// ---------------------------------------------------------------------------
// Fused attention: per block = one (b, h, 64-query tile).
// Phase 1: scores = Qs^T Ks (Q pre-scaled 1/8), write to d_out + keep in smem.
// Phase 2: warp softmax with HF additive mask over Sk=512.
// Phase 3: context = P @ V, write to d_out.
// 512 threads. Dynamic smem 182272 B.
// ---------------------------------------------------------------------------
__global__ void __launch_bounds__(512)
attn_kernel(const int* __restrict__ mask,
            float* __restrict__ out_ctx, float* __restrict__ out_scores)
{
    extern __shared__ float sm[];
    float* Qst  = sm;                       // [64][64]  (d-major)
    float* KV   = sm + 64 * 64;             // [64][128] Kst chunk  OR [128][64] V chunk
    float* Ss   = KV + 64 * 128;            // [64][512]
    float* madd = Ss + 64 * 512;            // [512]

    const int tid = threadIdx.x;
    const int q0  = blockIdx.x * 64;
    const int h   = blockIdx.y;
    const int b   = blockIdx.z;
    const int bh  = b * NH_ + h;

    // load Q tile (transposed layout in gmem already: [d][q])
    {
        const float* src = g_Qt + (size_t)bh * HD_ * SQ_;
        #pragma unroll
        for (int p = 0; p < 2; p++) {
            int idx = tid + p * 512;
            int d = idx >> 4;
            int c = (idx & 15) << 2;
            *(float4*)&Qst[d * 64 + c] = *(const float4*)(src + (size_t)d * SQ_ + q0 + c);
        }
    }
    // additive mask: (1 - mask) * finfo(f32).min
    madd[tid & 511] = (1.0f - (float)mask[b * SK_ + (tid & 511)]) * (-3.402823466e38f);

    const int tq = tid >> 5;   // 0..15 -> 4 q rows
    const int tk = tid & 31;   // 0..31 -> 4 k cols (within 128 chunk)

    // ---- Phase 1: scores ----
    for (int kc = 0; kc < 4; kc++) {
        __syncthreads();
        {   // load K chunk [d=64][k=128] (gmem layout matches: [d][k])
            const float* src = g_Kt + (size_t)bh * HD_ * SK_ + kc * 128;
            #pragma unroll
            for (int p = 0; p < 4; p++) {
                int idx = tid + p * 512;
                int d = idx >> 5;
                int c = (idx & 31) << 2;
                *(float4*)&KV[d * 128 + c] = *(const float4*)(src + (size_t)d * SK_ + c);
            }
        }
        __syncthreads();

        float acc[4][4];
        #pragma unroll
        for (int i = 0; i < 4; i++)
            #pragma unroll
            for (int j = 0; j < 4; j++) acc[i][j] = 0.0f;

        #pragma unroll 16
        for (int d = 0; d < 64; d++) {
            float4 a  = *(float4*)&Qst[d * 64 + tq * 4];
            float4 bb = *(float4*)&KV [d * 128 + tk * 4];
            float av[4] = {a.x, a.y, a.z, a.w};
            float bv[4] = {bb.x, bb.y, bb.z, bb.w};
            #pragma unroll
            for (int i = 0; i < 4; i++)
                #pragma unroll
                for (int j = 0; j < 4; j++)
                    acc[i][j] = fmaf(av[i], bv[j], acc[i][j]);
        }

        const size_t sbase = ((size_t)bh * SQ_ + q0) * SK_;
        #pragma unroll
        for (int i = 0; i < 4; i++) {
            int q = tq * 4 + i;
            float4 v = make_float4(acc[i][0], acc[i][1], acc[i][2], acc[i][3]);
            *(float4*)&Ss[q * 512 + kc * 128 + tk * 4] = v;
            *(float4*)&out_scores[sbase + (size_t)q * SK_ + kc * 128 + tk * 4] = v;
        }
    }
    __syncthreads();

    // ---- Phase 2: softmax (one warp owns 4 rows) ----
    {
        int w = tid >> 5, lane = tid & 31;
        for (int r = 0; r < 4; r++) {
            int q = w * 4 + r;
            float v[16];
            float mx = -3.402823466e38f;
            #pragma unroll
            for (int j = 0; j < 16; j++) {
                int k = lane + 32 * j;
                v[j] = Ss[q * 512 + k] + madd[k];
                mx = fmaxf(mx, v[j]);
            }
            #pragma unroll
            for (int o = 16; o > 0; o >>= 1)
                mx = fmaxf(mx, __shfl_xor_sync(0xffffffffu, mx, o));
            float s = 0.0f;
            #pragma unroll
            for (int j = 0; j < 16; j++) { v[j] = __expf(v[j] - mx); s += v[j]; }
            #pragma unroll
            for (int o = 16; o > 0; o >>= 1)
                s += __shfl_xor_sync(0xffffffffu, s, o);
            float inv = 1.0f / s;
            #pragma unroll
            for (int j = 0; j < 16; j++)
                Ss[q * 512 + lane + 32 * j] = v[j] * inv;
        }
    }

    // ---- Phase 3: context = P @ V ----
    const int tq2 = tid >> 4;  // 0..31 -> 2 q rows
    const int td  = tid & 15;  // 0..15 -> 4 d cols
    float pacc[2][4];
    #pragma unroll
    for (int i = 0; i < 2; i++)
        #pragma unroll
        for (int j = 0; j < 4; j++) pacc[i][j] = 0.0f;

    for (int kc = 0; kc < 4; kc++) {
        __syncthreads();
        {   // load V chunk [k=128][d=64]
            const float* src = g_V + ((size_t)bh * SK_ + kc * 128) * HD_;
            #pragma unroll
            for (int p = 0; p < 4; p++) {
                int idx = tid + p * 512;
                int kk = idx >> 4;
                int c  = (idx & 15) << 2;
                *(float4*)&KV[kk * 64 + c] = *(const float4*)(src + (size_t)kk * 64 + c);
            }
        }
        __syncthreads();

        #pragma unroll 8
        for (int k = 0; k < 128; k++) {
            float a0 = Ss[(tq2 * 2 + 0) * 512 + kc * 128 + k];
            float a1 = Ss[(tq2 * 2 + 1) * 512 + kc * 128 + k];
            float4 bv = *(float4*)&KV[k * 64 + td * 4];
            pacc[0][0] = fmaf(a0, bv.x, pacc[0][0]);
            pacc[0][1] = fmaf(a0, bv.y, pacc[0][1]);
            pacc[0][2] = fmaf(a0, bv.z, pacc[0][2]);
            pacc[0][3] = fmaf(a0, bv.w, pacc[0][3]);
            pacc[1][0] = fmaf(a1, bv.x, pacc[1][0]);
            pacc[1][1] = fmaf(a1, bv.y, pacc[1][1]);
            pacc[1][2] = fmaf(a1, bv.z, pacc[1][2]);
            pacc[1][3] = fmaf(a1, bv.w, pacc[1][3]);
        }
    }

    #pragma unroll
    for (int i = 0; i < 2; i++) {
        int q = q0 + tq2 * 2 + i;
        float4 v = make_float4(pacc[i][0], pacc[i][1], pacc[i][2], pacc[i][3]);
        *(float4*)&out_ctx[((size_t)b * SQ_ + q) * HID_ + h * 64 + td * 4] = v;
    }
}

// ---------------------------------------------------------------------------
extern "C" void kernel_launch(void* const* d_in, const int* in_sizes, int n_in,
                              void* d_out, int out_size)
{
    (void)in_sizes; (void)n_in; (void)out_size;
    const float* hs   = (const float*)d_in[0];
    const float* ehs  = (const float*)d_in[1];
    const int*   mask = (const int*)d_in[2];
    const float* Wq   = (const float*)d_in[3];
    const float* Wk   = (const float*)d_in[4];
    const float* Wv   = (const float*)d_in[5];

    float* out_ctx = (float*)d_out;
    float* out_sc  = out_ctx + (size_t)B_ * SQ_ * HID_;

    float *pQ, *pK, *pV;
    cudaGetSymbolAddress((void**)&pQ, g_Qt);
    cudaGetSymbolAddress((void**)&pK, g_Kt);
    cudaGetSymbolAddress((void**)&pV, g_V);

    const int attn_smem = (64*64 + 64*128 + 64*512 + 512) * 4;  // 182272 B
    cudaFuncSetAttribute(attn_kernel, cudaFuncAttributeMaxDynamicSharedMemorySize, attn_smem);

    // QKV projections (Q pre-scaled by 1/sqrt(HD)=0.125, Q/K transposed to [bh][d][s])
    dim3 gq(HID_ / 128, (B_ * SQ_) / 128);   // (8, 32)
    dim3 gk(HID_ / 128, (B_ * SK_) / 128);   // (8, 8)
    gemm_qkv<1><<<gq, 256>>>(hs,  Wq, pQ, SQ_, 0.125f);
    gemm_qkv<1><<<gk, 256>>>(ehs, Wk, pK, SK_, 1.0f);
    gemm_qkv<0><<<gk, 256>>>(ehs, Wv, pV, SK_, 1.0f);

    // Fused attention
    dim3 ga(SQ_ / 64, NH_, B_);              // (32, 16, 2)
    attn_kernel<<<ga, 512, attn_smem>>>(mask, out_ctx, out_sc);
}